// round 17
// baseline (speedup 1.0000x reference)
#include <cuda_runtime.h>
#include <cstdint>

#define N_SPARSE 16
#define N_VARLEN 4
#define SEQ_L 50
#define VOCAB 1000000
#define EPSV 1e-8f
#define ROW_LEN (N_SPARSE + N_VARLEN * SEQ_L)   // 216
#define OUT_LEN (N_SPARSE + N_VARLEN)           // 20
#define WARPS_PER_BLOCK 8
#define THREADS (WARPS_PER_BLOCK * 32)          // 256
#define TAIL (SEQ_L - 32)                        // 18
#define SLOTS 9                                  // 1 sparse + 4 ida + 4 idb

__device__ __forceinline__ void cpa4(uint32_t dst_smem, const float* src) {
    asm volatile("cp.async.ca.shared.global [%0], [%1], 4;"
                 :: "r"(dst_smem), "l"(src));
}

__global__ __launch_bounds__(THREADS) void emb_pool_kernel(
    const int* __restrict__ X,
    const float* __restrict__ sparse_tables,
    const float* __restrict__ varlen_tables,
    float* __restrict__ out)
{
    // [warp][slot][lane]: each slot row = 128B, conflict-free lane reads.
    __shared__ float gbuf[WARPS_PER_BLOCK][SLOTS][32];

    const int lane = threadIdx.x & 31;
    const int w    = threadIdx.x >> 5;
    const int row  = blockIdx.x * WARPS_PER_BLOCK + w;
    const int* __restrict__ xr = X + (size_t)row * ROW_LEN;
    const bool tail_on = (lane < TAIL);

    // ---- Phase 1: all id loads (coalesced, independent, no barrier) ----
    int sid = (lane < N_SPARSE) ? xr[lane] : 0;
    int ida[N_VARLEN], idb[N_VARLEN];
    #pragma unroll
    for (int v = 0; v < N_VARLEN; v++) {
        const int* ids = xr + N_SPARSE + v * SEQ_L;
        ida[v] = ids[lane];
        idb[v] = tail_on ? ids[32 + lane] : 0;   // id 0 -> valid table addr
    }

    // ---- Phase 2: gathers via cp.async (LDGSTS path, no register return) ----
    const uint32_t lane_base =
        (uint32_t)__cvta_generic_to_shared(&gbuf[w][0][lane]);

    if (lane < N_SPARSE)
        cpa4(lane_base + 0 * 128, sparse_tables + (size_t)lane * VOCAB + sid);
    else
        gbuf[w][0][lane] = 0.f;   // own-lane STS; ordered before own LDS

    #pragma unroll
    for (int v = 0; v < N_VARLEN; v++)
        cpa4(lane_base + (1 + v) * 128, varlen_tables + (size_t)v * VOCAB + ida[v]);
    #pragma unroll
    for (int v = 0; v < N_VARLEN; v++)
        cpa4(lane_base + (5 + v) * 128, varlen_tables + (size_t)v * VOCAB + idb[v]);

    asm volatile("cp.async.commit_group;");

    // ---- Phase 3: counts via ballot (overlaps with in-flight copies) ----
    int cnt[N_VARLEN];
    #pragma unroll
    for (int v = 0; v < N_VARLEN; v++) {
        unsigned b0 = __ballot_sync(0xffffffffu, ida[v] != 0);
        unsigned b1 = __ballot_sync(0xffffffffu, idb[v] != 0);
        cnt[v] = __popc(b0) + __popc(b1);
    }

    // Each thread reads only cells IT filled -> wait_group alone suffices.
    asm volatile("cp.async.wait_group 0;" ::: "memory");

    // ---- Phase 4: readback + mask + sum reductions ----
    float sparse_val = gbuf[w][0][lane];

    float s[N_VARLEN];
    #pragma unroll
    for (int v = 0; v < N_VARLEN; v++) {
        float a = (ida[v] != 0) ? gbuf[w][1 + v][lane] : 0.f;
        float b = (idb[v] != 0) ? gbuf[w][5 + v][lane] : 0.f;
        s[v] = a + b;
    }
    #pragma unroll
    for (int o = 16; o; o >>= 1) {
        #pragma unroll
        for (int v = 0; v < N_VARLEN; v++)
            s[v] += __shfl_xor_sync(0xffffffffu, s[v], o);
    }

    // ---- Phase 5: single coalesced store, lanes 0..19 ----
    float val;
    if (lane < N_SPARSE) {
        val = sparse_val;
    } else {
        float sv, cv;
        if      (lane == 16) { sv = s[0]; cv = (float)cnt[0]; }
        else if (lane == 17) { sv = s[1]; cv = (float)cnt[1]; }
        else if (lane == 18) { sv = s[2]; cv = (float)cnt[2]; }
        else                 { sv = s[3]; cv = (float)cnt[3]; }
        val = __fdividef(sv, cv + EPSV);
    }
    if (lane < OUT_LEN)
        __stcs(out + (size_t)row * OUT_LEN + lane, val);
}

extern "C" void kernel_launch(void* const* d_in, const int* in_sizes, int n_in,
                              void* d_out, int out_size)
{
    const int*   X  = (const int*)d_in[0];
    const float* st = (const float*)d_in[1];
    const float* vt = (const float*)d_in[2];
    float* out = (float*)d_out;

    const int B = in_sizes[0] / ROW_LEN;       // 16384
    const int grid = B / WARPS_PER_BLOCK;      // 2048

    emb_pool_kernel<<<grid, THREADS>>>(X, st, vt, out);
}